// round 3
// baseline (speedup 1.0000x reference)
#include <cuda_runtime.h>
#include <math_constants.h>

#define KVOL 27
#define C4_TOTAL 24             // 96 channels = 24 float4 (full row stride)
#define C4_HALF  12             // 48 channels per pass
#define ROWS_PER_BLOCK 32       // 12*32 = 384 threads

// Flag: 1 if neighbor_map is stored as int64, 0 if int32.
__device__ int g_idx_is64;

__global__ void detect_idx_dtype(const void* __restrict__ nmap,
                                 long long n_in_rows, int elem_count) {
    const long long* p = (const long long*)nmap;
    int n_check = 64;
    int avail = elem_count / 2;
    if (avail < n_check) n_check = avail;
    int ok64 = 1;
    for (int i = 0; i < n_check; ++i) {
        long long v = p[i];
        if (v < 0 || v >= n_in_rows) { ok64 = 0; break; }
    }
    g_idx_is64 = ok64;
}

__device__ __forceinline__ void vmax(float4& m, const float4 v) {
    m.x = fmaxf(m.x, v.x);
    m.y = fmaxf(m.y, v.y);
    m.z = fmaxf(m.z, v.z);
    m.w = fmaxf(m.w, v.w);
}

template <typename IDX>
__device__ __forceinline__ void pool_row(const float4* __restrict__ feat,
                                         const IDX* __restrict__ nm,
                                         float4* __restrict__ outp) {
    float4 m = make_float4(-CUDART_INF_F, -CUDART_INF_F, -CUDART_INF_F, -CUDART_INF_F);
    #pragma unroll
    for (int kb = 0; kb < KVOL; kb += 9) {
        int idx[9];                                    // 400000 rows: int is safe
        #pragma unroll
        for (int j = 0; j < 9; ++j)
            idx[j] = (int)__ldcs(&nm[kb + j]);         // streaming: don't pollute L2
        float4 v[9];
        #pragma unroll
        for (int j = 0; j < 9; ++j)
            v[j] = __ldg(feat + (long long)idx[j] * C4_TOTAL);  // 9 x 16B in flight
        #pragma unroll
        for (int j = 0; j < 9; ++j)
            vmax(m, v[j]);
    }
    __stcs(outp, m);                                   // streaming store
}

// One pass over all output rows, covering 48 channels starting at c4_base.
__global__ __launch_bounds__(C4_HALF * ROWS_PER_BLOCK)
void sparse_maxpool_half(const float4* __restrict__ in_feat,
                         const void* __restrict__ nmap,
                         float4* __restrict__ out,
                         int n_out, int c4_base) {
    int row = blockIdx.x * ROWS_PER_BLOCK + threadIdx.y;
    if (row >= n_out) return;
    int c4 = c4_base + threadIdx.x;                    // channel-quad within row

    const float4* feat_c = in_feat + c4;
    float4* outp = out + (long long)row * C4_TOTAL + c4;

    if (g_idx_is64) {
        const long long* nm = (const long long*)nmap + (long long)row * KVOL;
        pool_row(feat_c, nm, outp);
    } else {
        const int* nm = (const int*)nmap + (long long)row * KVOL;
        pool_row(feat_c, nm, outp);
    }
}

extern "C" void kernel_launch(void* const* d_in, const int* in_sizes, int n_in,
                              void* d_out, int out_size) {
    const float4* in_feat = (const float4*)d_in[0];
    const void*   nmap    = (const void*)d_in[1];
    float4*       out     = (float4*)d_out;

    int nmap_elems      = in_sizes[1];                    // N_OUT * KVOL
    int n_out           = nmap_elems / KVOL;              // 100000
    long long n_in_rows = (long long)in_sizes[0] / 96;    // 400000

    detect_idx_dtype<<<1, 1>>>(nmap, n_in_rows, nmap_elems);

    dim3 block(C4_HALF, ROWS_PER_BLOCK);
    int grid = (n_out + ROWS_PER_BLOCK - 1) / ROWS_PER_BLOCK;
    // Two sequential passes: each pass's in_feat footprint (76.8 MB of
    // sectors) fits in the 126 MB L2, converting random-gather reuse (6.75x)
    // into L2 hits instead of DRAM capacity misses.
    sparse_maxpool_half<<<grid, block>>>(in_feat, nmap, out, n_out, 0);
    sparse_maxpool_half<<<grid, block>>>(in_feat, nmap, out, n_out, C4_HALF);
}

// round 5
// speedup vs baseline: 1.1586x; 1.1586x over previous
#include <cuda_runtime.h>
#include <math_constants.h>

#define KVOL 27
#define C4   24                 // 96 channels = 24 float4
#define ROWS_PER_BLOCK 16       // 24*16 = 384 threads

// Flag: 1 if neighbor_map is stored as int64, 0 if int32.
__device__ int g_idx_is64;

__global__ void detect_idx_dtype(const void* __restrict__ nmap,
                                 long long n_in_rows, int elem_count) {
    // 64 parallel probes; int32 data interpreted as int64 lands outside
    // [0, n_in_rows) with overwhelming probability.
    const long long* p = (const long long*)nmap;
    int avail = elem_count / 2;
    int i = threadIdx.x;
    int bad = 0;
    if (i < avail) {
        long long v = p[i];
        bad = (v < 0 || v >= n_in_rows);
    }
    unsigned any_bad = __ballot_sync(0xFFFFFFFFu, bad);
    __shared__ unsigned s[2];
    if ((threadIdx.x & 31) == 0) s[threadIdx.x >> 5] = any_bad;
    __syncthreads();
    if (threadIdx.x == 0) g_idx_is64 = ((s[0] | s[1]) == 0u) ? 1 : 0;
}

// L2 access policy: fraction 1.0 evict_last -> keep in_feat lines resident.
__device__ __forceinline__ unsigned long long mk_keep_policy() {
    unsigned long long pol;
    asm("createpolicy.fractional.L2::evict_last.b64 %0, 1.0;" : "=l"(pol));
    return pol;
}

// in_feat gather load with the evict_last cache policy (128-bit legal form).
__device__ __forceinline__ float4 ldg_keep(const float4* p, unsigned long long pol) {
    float4 v;
    asm("ld.global.nc.L2::cache_hint.v4.f32 {%0,%1,%2,%3}, [%4], %5;"
        : "=f"(v.x), "=f"(v.y), "=f"(v.z), "=f"(v.w) : "l"(p), "l"(pol));
    return v;
}

__device__ __forceinline__ void vmax(float4& m, const float4 v) {
    m.x = fmaxf(m.x, v.x);
    m.y = fmaxf(m.y, v.y);
    m.z = fmaxf(m.z, v.z);
    m.w = fmaxf(m.w, v.w);
}

template <typename IDX>
__device__ __forceinline__ void pool_row(const float4* __restrict__ feat,
                                         const IDX* __restrict__ nm,
                                         float4* __restrict__ outp) {
    const unsigned long long pol = mk_keep_policy();
    float4 m = make_float4(-CUDART_INF_F, -CUDART_INF_F, -CUDART_INF_F, -CUDART_INF_F);
    #pragma unroll
    for (int kb = 0; kb < KVOL; kb += 9) {
        int idx[9];                                    // 400000 rows: int is safe
        #pragma unroll
        for (int j = 0; j < 9; ++j)
            idx[j] = (int)__ldcs(&nm[kb + j]);         // streaming: don't pollute L2
        float4 v[9];
        #pragma unroll
        for (int j = 0; j < 9; ++j)
            v[j] = ldg_keep(feat + (long long)idx[j] * C4, pol);  // 9 x 16B in flight
        #pragma unroll
        for (int j = 0; j < 9; ++j)
            vmax(m, v[j]);
    }
    __stcs(outp, m);                                   // streaming store
}

__global__ __launch_bounds__(C4 * ROWS_PER_BLOCK)
void sparse_maxpool_kernel(const float4* __restrict__ in_feat,
                           const void* __restrict__ nmap,
                           float4* __restrict__ out,
                           int n_out) {
    int row = blockIdx.x * ROWS_PER_BLOCK + threadIdx.y;
    if (row >= n_out) return;
    int c4 = threadIdx.x;                              // 0..23

    const float4* feat_c = in_feat + c4;
    float4* outp = out + (long long)row * C4 + c4;

    if (g_idx_is64) {
        const long long* nm = (const long long*)nmap + (long long)row * KVOL;
        pool_row(feat_c, nm, outp);
    } else {
        const int* nm = (const int*)nmap + (long long)row * KVOL;
        pool_row(feat_c, nm, outp);
    }
}

extern "C" void kernel_launch(void* const* d_in, const int* in_sizes, int n_in,
                              void* d_out, int out_size) {
    const float4* in_feat = (const float4*)d_in[0];
    const void*   nmap    = (const void*)d_in[1];
    float4*       out     = (float4*)d_out;

    int nmap_elems      = in_sizes[1];                    // N_OUT * KVOL
    int n_out           = nmap_elems / KVOL;              // 100000
    long long n_in_rows = (long long)in_sizes[0] / 96;    // 400000

    detect_idx_dtype<<<1, 64>>>(nmap, n_in_rows, nmap_elems);

    dim3 block(C4, ROWS_PER_BLOCK);
    int grid = (n_out + ROWS_PER_BLOCK - 1) / ROWS_PER_BLOCK;
    sparse_maxpool_kernel<<<grid, block>>>(in_feat, nmap, out, n_out);
}